// round 8
// baseline (speedup 1.0000x reference)
#include <cuda_runtime.h>
#include <cstdint>

#define BB   16
#define NSS  128
#define TT   64
#define DD   512
#define HH   512
#define NB_LSTM 128

// ---------------- scratch (device globals) ----------------
__device__ float g_attn_feat[BB * NSS * HH];
__device__ float g_hop_feat [BB * NSS * HH];
__device__ float g_xcat     [TT * BB * DD];      // row = t*16+b
__device__ float g_X        [TT * BB * 4 * HH];  // gate preacts
__device__ float g_qa       [BB * TT * HH];      // row = b*64+t
__device__ float g_qb       [BB * TT * HH];
__device__ float g_qw       [BB * TT * HH];
__device__ float g_hbuf     [2][BB * HH];
__device__ unsigned g_flag  [TT * NB_LSTM * 8];  // 32B-stride per-CTA step flags

// ---------------- helpers ----------------
__device__ __forceinline__ float fast_tanh(float x) {
    float e, r;
    asm("ex2.approx.f32 %0, %1;" : "=f"(e) : "f"(x * 2.885390081777927f));
    asm("rcp.approx.f32 %0, %1;" : "=f"(r) : "f"(e + 1.0f));
    return fmaf(-2.0f, r, 1.0f);
}
__device__ __forceinline__ float sigm(float x) { return 1.0f / (1.0f + __expf(-x)); }

// packed fp32 pair FMA (Blackwell f32x2): d = a*b + c elementwise on (lo,hi)
__device__ __forceinline__ unsigned long long ffma2(
    unsigned long long a, unsigned long long b, unsigned long long c) {
    unsigned long long d;
    asm("fma.rn.f32x2 %0, %1, %2, %3;" : "=l"(d) : "l"(a), "l"(b), "l"(c));
    return d;
}
__device__ __forceinline__ float pairsum(unsigned long long v) {
    float lo, hi;
    asm("mov.b64 {%0, %1}, %2;" : "=f"(lo), "=f"(hi) : "l"(v));
    return lo + hi;
}

// ============ BIG SGEMM: 128x128 tile, BK=8, 256 threads, 8x8 micro ============
#define SBS 132
template<bool TRANSB, bool BIAS>
__global__ void __launch_bounds__(256) sgemm_big(
    const float* __restrict__ A,
    const float* __restrict__ B0, const float* __restrict__ B1,
    const float* __restrict__ bi1, const float* __restrict__ bi2,
    float* __restrict__ C0, float* __restrict__ C1,
    int M, int N, int K)
{
    const float* __restrict__ Bm = blockIdx.z ? B1 : B0;
    float* __restrict__ C = blockIdx.z ? C1 : C0;

    __shared__ float As[2][8 * SBS];
    __shared__ float Bs[2][8 * SBS];

    const int tid = threadIdx.x;
    const int m0 = blockIdx.y * 128, n0 = blockIdx.x * 128;
    const int row0 = (tid >> 4) << 3;
    const int col0 = (tid & 15) << 3;

    const int am = tid >> 1, akq = (tid & 1) << 2;
    const float* Ap = A + (size_t)(m0 + am) * K + akq;
    int bn = 0, bkq = 0, bkr = 0, bn4 = 0;
    const float* Bp;
    if (TRANSB) { bn = tid >> 1; bkq = (tid & 1) << 2; Bp = Bm + (size_t)(n0 + bn) * K + bkq; }
    else        { bkr = tid >> 5; bn4 = (tid & 31) << 2; Bp = Bm + (size_t)bkr * N + n0 + bn4; }

    float acc[8][8] = {};
    float4 av, bv;

    av = *(const float4*)(Ap);
    bv = *(const float4*)(Bp);
    {
        float* as = As[0];
        as[(akq+0)*SBS + am] = av.x; as[(akq+1)*SBS + am] = av.y;
        as[(akq+2)*SBS + am] = av.z; as[(akq+3)*SBS + am] = av.w;
        float* bs = Bs[0];
        if (TRANSB) {
            bs[(bkq+0)*SBS + bn] = bv.x; bs[(bkq+1)*SBS + bn] = bv.y;
            bs[(bkq+2)*SBS + bn] = bv.z; bs[(bkq+3)*SBS + bn] = bv.w;
        } else {
            *(float4*)(bs + bkr*SBS + bn4) = bv;
        }
    }
    __syncthreads();

    int buf = 0;
    for (int k0 = 8; k0 <= K; k0 += 8) {
        const bool more = (k0 < K);
        if (more) {
            av = *(const float4*)(Ap + k0);
            if (TRANSB) bv = *(const float4*)(Bp + k0);
            else        bv = *(const float4*)(Bm + (size_t)(k0 + bkr) * N + n0 + bn4);
        }
        const float* as = As[buf];
        const float* bs = Bs[buf];
#pragma unroll
        for (int kk = 0; kk < 8; kk++) {
            float4 a0 = *(const float4*)(as + kk*SBS + row0);
            float4 a1 = *(const float4*)(as + kk*SBS + row0 + 4);
            float4 c0 = *(const float4*)(bs + kk*SBS + col0);
            float4 c1 = *(const float4*)(bs + kk*SBS + col0 + 4);
            float aa[8] = {a0.x,a0.y,a0.z,a0.w,a1.x,a1.y,a1.z,a1.w};
            float bb[8] = {c0.x,c0.y,c0.z,c0.w,c1.x,c1.y,c1.z,c1.w};
#pragma unroll
            for (int i = 0; i < 8; i++)
#pragma unroll
                for (int j = 0; j < 8; j++) acc[i][j] = fmaf(aa[i], bb[j], acc[i][j]);
        }
        if (more) {
            float* asn = As[buf ^ 1];
            asn[(akq+0)*SBS + am] = av.x; asn[(akq+1)*SBS + am] = av.y;
            asn[(akq+2)*SBS + am] = av.z; asn[(akq+3)*SBS + am] = av.w;
            float* bsn = Bs[buf ^ 1];
            if (TRANSB) {
                bsn[(bkq+0)*SBS + bn] = bv.x; bsn[(bkq+1)*SBS + bn] = bv.y;
                bsn[(bkq+2)*SBS + bn] = bv.z; bsn[(bkq+3)*SBS + bn] = bv.w;
            } else {
                *(float4*)(bsn + bkr*SBS + bn4) = bv;
            }
        }
        __syncthreads();
        buf ^= 1;
    }

    float bias[8] = {};
    if (BIAS) {
#pragma unroll
        for (int j = 0; j < 8; j++) bias[j] = bi1[n0+col0+j] + bi2[n0+col0+j];
    }
#pragma unroll
    for (int i = 0; i < 8; i++) {
        float4 o0 = {acc[i][0]+bias[0], acc[i][1]+bias[1], acc[i][2]+bias[2], acc[i][3]+bias[3]};
        float4 o1 = {acc[i][4]+bias[4], acc[i][5]+bias[5], acc[i][6]+bias[6], acc[i][7]+bias[7]};
        float* cp = C + (size_t)(m0 + row0 + i) * N + n0 + col0;
        *(float4*)(cp)     = o0;
        *(float4*)(cp + 4) = o1;
    }
}

// ============ SMALL SGEMM: 64x64 tile, 256 threads, 4x4 micro ============
__global__ void __launch_bounds__(256) sgemm_small(
    const float* __restrict__ A, const float* __restrict__ Bm,
    float* __restrict__ C, int M, int N, int K)
{
    __shared__ float As[16][68];
    __shared__ float Bs[16][68];
    const int tid = threadIdx.x;
    const int m0 = blockIdx.y * 64, n0 = blockIdx.x * 64;
    const int tx = (tid & 15) << 2, ty = (tid >> 4) << 2;
    const int lr = tid >> 2, lk = (tid & 3) << 2;
    const int bkr = tid >> 4, bnc = (tid & 15) << 2;
    float acc[4][4] = {};

    for (int k0 = 0; k0 < K; k0 += 16) {
        float4 av = *(const float4*)(A + (size_t)(m0 + lr) * K + k0 + lk);
        As[lk+0][lr] = av.x; As[lk+1][lr] = av.y; As[lk+2][lr] = av.z; As[lk+3][lr] = av.w;
        float4 bv = *(const float4*)(Bm + (size_t)(k0 + bkr) * N + n0 + bnc);
        *(float4*)(&Bs[bkr][bnc]) = bv;
        __syncthreads();
#pragma unroll
        for (int kk = 0; kk < 16; kk++) {
            float4 a = *(const float4*)(&As[kk][ty]);
            float4 b = *(const float4*)(&Bs[kk][tx]);
            acc[0][0] += a.x*b.x; acc[0][1] += a.x*b.y; acc[0][2] += a.x*b.z; acc[0][3] += a.x*b.w;
            acc[1][0] += a.y*b.x; acc[1][1] += a.y*b.y; acc[1][2] += a.y*b.z; acc[1][3] += a.y*b.w;
            acc[2][0] += a.z*b.x; acc[2][1] += a.z*b.y; acc[2][2] += a.z*b.z; acc[2][3] += a.z*b.w;
            acc[3][0] += a.w*b.x; acc[3][1] += a.w*b.y; acc[3][2] += a.w*b.z; acc[3][3] += a.w*b.w;
        }
        __syncthreads();
    }
#pragma unroll
    for (int i = 0; i < 4; i++) {
        float4 o = {acc[i][0], acc[i][1], acc[i][2], acc[i][3]};
        *(float4*)(C + (size_t)(m0+ty+i) * N + n0 + tx) = o;
    }
}

// ---------------- prep: xcat + maxpool + h0 + flag reset ----------------
__global__ void prep_kernel(const float* __restrict__ attn_mem,
                            const float* __restrict__ lstm_in,
                            const float* __restrict__ init_h,
                            const int* __restrict__ msz)
{
    const int t = blockIdx.x, b = blockIdx.y, d = threadIdx.x;
    // zero the LSTM step flags (stream-ordered before lstm_kernel)
    {
        const int bid = b * TT + t;          // 0..1023
        if (d < 64) g_flag[bid * 64 + d] = 0u;   // 1024*64 = 65536 words
    }
    if (t == 0) {
        const int ms = msz[b];
        float m = -3.0e38f;
        for (int n = 0; n < ms; n++)
            m = fmaxf(m, attn_mem[((size_t)b * NSS + n) * DD + d]);
        g_xcat[(size_t)b * DD + d] = m;
        g_hbuf[0][b * HH + d] = init_h[d];
    } else {
        g_xcat[((size_t)t * BB + b) * DD + d] =
            lstm_in[((size_t)b * (TT - 1) + (t - 1)) * DD + d];
    }
}

// ---------------- persistent LSTM: 128 CTAs, flag-based grid barrier ----------------
// Thread tile: 4 gate-rows x 4 batches x 32 k; f32x2 packed accumulation.
__global__ void __launch_bounds__(256) lstm_kernel(const float* __restrict__ Whh,
                                                   const float* __restrict__ init_c)
{
    __shared__ float h_sm[16][516];        // 33 KB; aliased as red after compute
    __shared__ float gsm[16][16];
    __shared__ float c_sm[16][4];

    float* red = &h_sm[0][0];              // [16 kc][260] scratch (aliased)

    const int tid = threadIdx.x;
    const int cta = blockIdx.x;
    const int hd0 = cta * 4;
    const int kc = tid & 15;
    const int rr = (tid >> 4) & 3;
    const int bq = tid >> 6;

    const float* wp0 = Whh + ((size_t)(0*HH + hd0 + rr)) * HH + kc * 4;
    const float* wp1 = Whh + ((size_t)(1*HH + hd0 + rr)) * HH + kc * 4;
    const float* wp2 = Whh + ((size_t)(2*HH + hd0 + rr)) * HH + kc * 4;
    const float* wp3 = Whh + ((size_t)(3*HH + hd0 + rr)) * HH + kc * 4;

    if (tid < 64) { int b = tid >> 2, l = tid & 3; c_sm[b][l] = init_c[hd0 + l]; }

    const int rowX = tid >> 4;
    const int bX   = tid & 15;

    for (int s = 0; s < TT; s++) {
        // prefetch this step's X preactivation (independent of h)
        float xv = __ldcg(&g_X[((size_t)s * BB + bX) * (4 * HH) + (rowX >> 2) * HH + hd0 + (rowX & 3)]);

        if (s > 0) {
            if (tid < NB_LSTM) {
                volatile unsigned* f = &g_flag[((s - 1) * NB_LSTM + tid) * 8];
                while (*f == 0u) { __nanosleep(20); }
            }
            __threadfence();   // acquire: order h loads after observed flags
        }
        __syncthreads();

        // stage h into h_sm[b][k]
        const float4* hb = (const float4*)g_hbuf[s & 1];
#pragma unroll
        for (int i2 = 0; i2 < 8; i2++) {
            int i = tid + 256 * i2;
            float4 hv = __ldcg(hb + i);
            int b = i >> 7, k4 = (i & 127) << 2;
            *(float4*)(&h_sm[b][k4]) = hv;
        }
        __syncthreads();

        unsigned long long acc[4][4];
#pragma unroll
        for (int g = 0; g < 4; g++)
#pragma unroll
            for (int bi = 0; bi < 4; bi++) acc[g][bi] = 0ULL;

#pragma unroll
        for (int j = 0; j < 8; j++) {
            const ulonglong2 w0 = *(const ulonglong2*)(wp0 + j * 64);
            const ulonglong2 w1 = *(const ulonglong2*)(wp1 + j * 64);
            const ulonglong2 w2 = *(const ulonglong2*)(wp2 + j * 64);
            const ulonglong2 w3 = *(const ulonglong2*)(wp3 + j * 64);
#pragma unroll
            for (int bi = 0; bi < 4; bi++) {
                const ulonglong2 h2 = *(const ulonglong2*)(&h_sm[bq * 4 + bi][kc * 4 + j * 64]);
                acc[0][bi] = ffma2(w0.x, h2.x, acc[0][bi]);
                acc[0][bi] = ffma2(w0.y, h2.y, acc[0][bi]);
                acc[1][bi] = ffma2(w1.x, h2.x, acc[1][bi]);
                acc[1][bi] = ffma2(w1.y, h2.y, acc[1][bi]);
                acc[2][bi] = ffma2(w2.x, h2.x, acc[2][bi]);
                acc[2][bi] = ffma2(w2.y, h2.y, acc[2][bi]);
                acc[3][bi] = ffma2(w3.x, h2.x, acc[3][bi]);
                acc[3][bi] = ffma2(w3.y, h2.y, acc[3][bi]);
            }
        }
        __syncthreads();   // h_sm reads done before aliasing as red

#pragma unroll
        for (int g = 0; g < 4; g++)
#pragma unroll
            for (int bi = 0; bi < 4; bi++)
                red[kc * 260 + (g * 4 + rr) * 16 + (bq * 4 + bi)] = pairsum(acc[g][bi]);
        __syncthreads();

        {
            float sum = xv;
#pragma unroll
            for (int i = 0; i < 16; i++) sum += red[i * 260 + rowX * 16 + bX];
            gsm[rowX][bX] = sum;
        }
        __syncthreads();

        if (tid < 64) {
            int b = tid >> 2, l = tid & 3;
            float gi = gsm[0 + l][b], gf = gsm[4 + l][b];
            float gg = gsm[8 + l][b], go = gsm[12 + l][b];
            float c = sigm(gf) * c_sm[b][l] + sigm(gi) * fast_tanh(gg);
            float h = sigm(go) * fast_tanh(c);
            c_sm[b][l] = c;
            g_hbuf[(s + 1) & 1][b * HH + hd0 + l] = h;
            g_qa[((size_t)b * TT + s) * HH + hd0 + l] = h;
            __threadfence();   // release: publish h before flag
        }
        __syncthreads();
        if (tid == 0 && s < TT - 1) {
            *((volatile unsigned*)&g_flag[(s * NB_LSTM + cta) * 8]) = 1u;
        }
    }
}

// ---------------- hop: 8 t per block; score+softmax+weighted-sum fused ----------------
__global__ void __launch_bounds__(256) hop_kernel(
    const float* __restrict__ qw, const float* __restrict__ feat,
    const float* __restrict__ v, const int* __restrict__ msz,
    float* __restrict__ qout)
{
    __shared__ float qsm[8 * HH];
    __shared__ float vsm[HH];
    __shared__ float p[8][NSS];
    __shared__ float4 part[8][HH / 4];

    const int tg = blockIdx.x, b = blockIdx.y, tid = threadIdx.x;
    const int t0 = tg * 8;
    const float* qbase = qw + ((size_t)b * TT + t0) * HH;
    {
        const float4* qsrc = reinterpret_cast<const float4*>(qbase);
        float4* qdst = reinterpret_cast<float4*>(qsm);
#pragma unroll
        for (int i = 0; i < 4; i++) qdst[tid + 256 * i] = qsrc[tid + 256 * i];
        vsm[tid] = v[tid]; vsm[tid + 256] = v[tid + 256];
    }
    __syncthreads();

    const int wid = tid >> 5, lane = tid & 31;
    const int ms = msz[b];
    const float* qt = qsm + wid * HH;
    for (int n = 0; n < NSS; n++) {
        const float* f = feat + ((size_t)b * NSS + n) * HH;
        float s = 0.f;
#pragma unroll 4
        for (int j = 0; j < 16; j++) {
            int k = lane + (j << 5);
            s += vsm[k] * fast_tanh(f[k] + qt[k]);
        }
#pragma unroll
        for (int o = 16; o; o >>= 1) s += __shfl_xor_sync(0xffffffffu, s, o);
        if (lane == 0) p[wid][n] = (n < ms) ? s : -1e30f;
    }
    __syncthreads();
    {
        float x0 = p[wid][lane], x1 = p[wid][lane+32], x2 = p[wid][lane+64], x3 = p[wid][lane+96];
        float m = fmaxf(fmaxf(x0, x1), fmaxf(x2, x3));
#pragma unroll
        for (int o = 16; o; o >>= 1) m = fmaxf(m, __shfl_xor_sync(0xffffffffu, m, o));
        float e0 = __expf(x0 - m), e1 = __expf(x1 - m), e2 = __expf(x2 - m), e3 = __expf(x3 - m);
        float s = e0 + e1 + e2 + e3;
#pragma unroll
        for (int o = 16; o; o >>= 1) s += __shfl_xor_sync(0xffffffffu, s, o);
        float inv = 1.f / s;
        p[wid][lane] = e0*inv; p[wid][lane+32] = e1*inv; p[wid][lane+64] = e2*inv; p[wid][lane+96] = e3*inv;
    }
    __syncthreads();
    {
        const int g = tid >> 7;
        const int hc = tid & 127;
        float4 acc[8] = {};
        const int nlo = g * 64;
#pragma unroll 2
        for (int n = nlo; n < nlo + 64; n++) {
            float4 fv = *reinterpret_cast<const float4*>(feat + ((size_t)b * NSS + n) * HH + hc * 4);
#pragma unroll
            for (int t = 0; t < 8; t++) {
                float pw = p[t][n];
                acc[t].x = fmaf(pw, fv.x, acc[t].x);
                acc[t].y = fmaf(pw, fv.y, acc[t].y);
                acc[t].z = fmaf(pw, fv.z, acc[t].z);
                acc[t].w = fmaf(pw, fv.w, acc[t].w);
            }
        }
        if (g == 1) {
#pragma unroll
            for (int t = 0; t < 8; t++) part[t][hc] = acc[t];
        }
        __syncthreads();
        if (g == 0) {
#pragma unroll
            for (int t = 0; t < 8; t++) {
                float4 pv = part[t][hc];
                float4 o = {acc[t].x + pv.x, acc[t].y + pv.y, acc[t].z + pv.z, acc[t].w + pv.w};
                *reinterpret_cast<float4*>(qout + ((size_t)b * TT + t0 + t) * HH + hc * 4) = o;
            }
        }
    }
}

// ---------------- final score (unmasked) ----------------
__global__ void __launch_bounds__(256) final_kernel(
    const float* __restrict__ qw, const float* __restrict__ feat,
    const float* __restrict__ v, float* __restrict__ out)
{
    __shared__ float qsm[HH];
    __shared__ float vsm[HH];
    const int t = blockIdx.x, b = blockIdx.y, tid = threadIdx.x;
    const float* qrow = qw + ((size_t)b * TT + t) * HH;
    qsm[tid] = qrow[tid]; qsm[tid + 256] = qrow[tid + 256];
    vsm[tid] = v[tid];    vsm[tid + 256] = v[tid + 256];
    __syncthreads();
    const int wid = tid >> 5, lane = tid & 31;
    for (int n = wid; n < NSS; n += 8) {
        const float* f = feat + ((size_t)b * NSS + n) * HH;
        float s = 0.f;
#pragma unroll 4
        for (int j = 0; j < 16; j++) {
            int k = lane + (j << 5);
            s += vsm[k] * fast_tanh(f[k] + qsm[k]);
        }
#pragma unroll
        for (int o = 16; o; o >>= 1) s += __shfl_xor_sync(0xffffffffu, s, o);
        if (lane == 0) out[(((size_t)b * TT) + t) * NSS + n] = s;
    }
}

extern "C" void kernel_launch(void* const* d_in, const int* in_sizes, int n_in,
                              void* d_out, int out_size)
{
    const float* attn_mem = (const float*)d_in[0];
    const float* lstm_in  = (const float*)d_in[1];
    const float* init_h   = (const float*)d_in[2];
    const float* init_c   = (const float*)d_in[3];
    const float* Wih      = (const float*)d_in[4];
    const float* Whh      = (const float*)d_in[5];
    const float* bih      = (const float*)d_in[6];
    const float* bhh      = (const float*)d_in[7];
    const float* attn_wm  = (const float*)d_in[8];
    const float* attn_wq  = (const float*)d_in[9];
    const float* attn_v   = (const float*)d_in[10];
    const float* hop_wm   = (const float*)d_in[11];
    const float* hop_wq   = (const float*)d_in[12];
    const float* hop_v    = (const float*)d_in[13];
    const int*   msz      = (const int*)d_in[14];
    float* out = (float*)d_out;

    float *afeat, *hfeat, *xcat, *X, *qa, *qb, *qwb;
    cudaGetSymbolAddress((void**)&afeat, g_attn_feat);
    cudaGetSymbolAddress((void**)&hfeat, g_hop_feat);
    cudaGetSymbolAddress((void**)&xcat,  g_xcat);
    cudaGetSymbolAddress((void**)&X,     g_X);
    cudaGetSymbolAddress((void**)&qa,    g_qa);
    cudaGetSymbolAddress((void**)&qb,    g_qb);
    cudaGetSymbolAddress((void**)&qwb,   g_qw);

    prep_kernel<<<dim3(TT, BB), DD>>>(attn_mem, lstm_in, init_h, msz);
    sgemm_big<false,false><<<dim3(4, 16, 2), 256>>>(attn_mem, attn_wm, hop_wm,
                                                    nullptr, nullptr, afeat, hfeat,
                                                    BB*NSS, HH, DD);
    sgemm_big<true, true ><<<dim3(16, 8, 1), 256>>>(xcat, Wih, nullptr,
                                                    bih, bhh, X, nullptr,
                                                    TT*BB, 4*HH, DD);
    lstm_kernel<<<NB_LSTM, 256>>>(Whh, init_c);
    // hop 1
    sgemm_small<<<dim3(8, 16), 256>>>(qa, hop_wq, qwb, BB*TT, HH, HH);
    hop_kernel<<<dim3(8, BB), 256>>>(qwb, hfeat, hop_v, msz, qb);
    // hop 2
    sgemm_small<<<dim3(8, 16), 256>>>(qb, hop_wq, qwb, BB*TT, HH, HH);
    hop_kernel<<<dim3(8, BB), 256>>>(qwb, hfeat, hop_v, msz, qa);
    // final
    sgemm_small<<<dim3(8, 16), 256>>>(qa, attn_wq, qwb, BB*TT, HH, HH);
    final_kernel<<<dim3(TT, BB), 256>>>(qwb, afeat, attn_v, out);
}

// round 9
// speedup vs baseline: 1.2050x; 1.2050x over previous
#include <cuda_runtime.h>
#include <cstdint>

#define BB   16
#define NSS  128
#define TT   64
#define DD   512
#define HH   512
#define NB_LSTM 128

// ---------------- scratch (device globals) ----------------
__device__ float g_attn_feat[BB * NSS * HH];
__device__ float g_hop_feat [BB * NSS * HH];
__device__ float g_xcat     [TT * BB * DD];      // row = t*16+b
__device__ float g_X        [TT * BB * 4 * HH];  // gate preacts
__device__ float g_qa       [BB * TT * HH];      // row = b*64+t
__device__ float g_qb       [BB * TT * HH];
__device__ float g_qw       [BB * TT * HH];
__device__ float g_hbuf     [2][BB * HH];
__device__ unsigned g_cnt   [TT + 1];            // zeroed by prep_kernel each launch

// ---------------- helpers ----------------
__device__ __forceinline__ float fast_tanh(float x) {
    float e, r;
    asm("ex2.approx.f32 %0, %1;" : "=f"(e) : "f"(x * 2.885390081777927f));
    asm("rcp.approx.f32 %0, %1;" : "=f"(r) : "f"(e + 1.0f));
    return fmaf(-2.0f, r, 1.0f);
}
__device__ __forceinline__ float sigm(float x) { return 1.0f / (1.0f + __expf(-x)); }

__device__ __forceinline__ unsigned long long ffma2(
    unsigned long long a, unsigned long long b, unsigned long long c) {
    unsigned long long d;
    asm("fma.rn.f32x2 %0, %1, %2, %3;" : "=l"(d) : "l"(a), "l"(b), "l"(c));
    return d;
}
__device__ __forceinline__ float pairsum(unsigned long long v) {
    float lo, hi;
    asm("mov.b64 {%0, %1}, %2;" : "=f"(lo), "=f"(hi) : "l"(v));
    return lo + hi;
}
// release-increment: orders this CTA's prior global writes (after __syncthreads) before the add
__device__ __forceinline__ void atom_add_release(unsigned* p) {
    unsigned old;
    asm volatile("atom.release.gpu.global.add.u32 %0, [%1], 1;"
                 : "=r"(old) : "l"(p) : "memory");
}
// acquire-load: subsequent reads (after __syncthreads) see producers' writes
__device__ __forceinline__ unsigned ld_acquire(const unsigned* p) {
    unsigned v;
    asm volatile("ld.acquire.gpu.global.u32 %0, [%1];" : "=r"(v) : "l"(p) : "memory");
    return v;
}

// ============ BIG SGEMM: 128x128 tile, BK=8, 256 threads, 8x8 micro ============
#define SBS 132
template<bool TRANSB, bool BIAS>
__global__ void __launch_bounds__(256) sgemm_big(
    const float* __restrict__ A,
    const float* __restrict__ B0, const float* __restrict__ B1,
    const float* __restrict__ bi1, const float* __restrict__ bi2,
    float* __restrict__ C0, float* __restrict__ C1,
    int M, int N, int K)
{
    const float* __restrict__ Bm = blockIdx.z ? B1 : B0;
    float* __restrict__ C = blockIdx.z ? C1 : C0;

    __shared__ float As[2][8 * SBS];
    __shared__ float Bs[2][8 * SBS];

    const int tid = threadIdx.x;
    const int m0 = blockIdx.y * 128, n0 = blockIdx.x * 128;
    const int row0 = (tid >> 4) << 3;
    const int col0 = (tid & 15) << 3;

    const int am = tid >> 1, akq = (tid & 1) << 2;
    const float* Ap = A + (size_t)(m0 + am) * K + akq;
    int bn = 0, bkq = 0, bkr = 0, bn4 = 0;
    const float* Bp;
    if (TRANSB) { bn = tid >> 1; bkq = (tid & 1) << 2; Bp = Bm + (size_t)(n0 + bn) * K + bkq; }
    else        { bkr = tid >> 5; bn4 = (tid & 31) << 2; Bp = Bm + (size_t)bkr * N + n0 + bn4; }

    float acc[8][8] = {};
    float4 av, bv;

    av = *(const float4*)(Ap);
    bv = *(const float4*)(Bp);
    {
        float* as = As[0];
        as[(akq+0)*SBS + am] = av.x; as[(akq+1)*SBS + am] = av.y;
        as[(akq+2)*SBS + am] = av.z; as[(akq+3)*SBS + am] = av.w;
        float* bs = Bs[0];
        if (TRANSB) {
            bs[(bkq+0)*SBS + bn] = bv.x; bs[(bkq+1)*SBS + bn] = bv.y;
            bs[(bkq+2)*SBS + bn] = bv.z; bs[(bkq+3)*SBS + bn] = bv.w;
        } else {
            *(float4*)(bs + bkr*SBS + bn4) = bv;
        }
    }
    __syncthreads();

    int buf = 0;
    for (int k0 = 8; k0 <= K; k0 += 8) {
        const bool more = (k0 < K);
        if (more) {
            av = *(const float4*)(Ap + k0);
            if (TRANSB) bv = *(const float4*)(Bp + k0);
            else        bv = *(const float4*)(Bm + (size_t)(k0 + bkr) * N + n0 + bn4);
        }
        const float* as = As[buf];
        const float* bs = Bs[buf];
#pragma unroll
        for (int kk = 0; kk < 8; kk++) {
            float4 a0 = *(const float4*)(as + kk*SBS + row0);
            float4 a1 = *(const float4*)(as + kk*SBS + row0 + 4);
            float4 c0 = *(const float4*)(bs + kk*SBS + col0);
            float4 c1 = *(const float4*)(bs + kk*SBS + col0 + 4);
            float aa[8] = {a0.x,a0.y,a0.z,a0.w,a1.x,a1.y,a1.z,a1.w};
            float bb[8] = {c0.x,c0.y,c0.z,c0.w,c1.x,c1.y,c1.z,c1.w};
#pragma unroll
            for (int i = 0; i < 8; i++)
#pragma unroll
                for (int j = 0; j < 8; j++) acc[i][j] = fmaf(aa[i], bb[j], acc[i][j]);
        }
        if (more) {
            float* asn = As[buf ^ 1];
            asn[(akq+0)*SBS + am] = av.x; asn[(akq+1)*SBS + am] = av.y;
            asn[(akq+2)*SBS + am] = av.z; asn[(akq+3)*SBS + am] = av.w;
            float* bsn = Bs[buf ^ 1];
            if (TRANSB) {
                bsn[(bkq+0)*SBS + bn] = bv.x; bsn[(bkq+1)*SBS + bn] = bv.y;
                bsn[(bkq+2)*SBS + bn] = bv.z; bsn[(bkq+3)*SBS + bn] = bv.w;
            } else {
                *(float4*)(bsn + bkr*SBS + bn4) = bv;
            }
        }
        __syncthreads();
        buf ^= 1;
    }

    float bias[8] = {};
    if (BIAS) {
#pragma unroll
        for (int j = 0; j < 8; j++) bias[j] = bi1[n0+col0+j] + bi2[n0+col0+j];
    }
#pragma unroll
    for (int i = 0; i < 8; i++) {
        float4 o0 = {acc[i][0]+bias[0], acc[i][1]+bias[1], acc[i][2]+bias[2], acc[i][3]+bias[3]};
        float4 o1 = {acc[i][4]+bias[4], acc[i][5]+bias[5], acc[i][6]+bias[6], acc[i][7]+bias[7]};
        float* cp = C + (size_t)(m0 + row0 + i) * N + n0 + col0;
        *(float4*)(cp)     = o0;
        *(float4*)(cp + 4) = o1;
    }
}

// ============ SMALL SGEMM: 64x64 tile, 256 threads, 4x4 micro ============
__global__ void __launch_bounds__(256) sgemm_small(
    const float* __restrict__ A, const float* __restrict__ Bm,
    float* __restrict__ C, int M, int N, int K)
{
    __shared__ float As[16][68];
    __shared__ float Bs[16][68];
    const int tid = threadIdx.x;
    const int m0 = blockIdx.y * 64, n0 = blockIdx.x * 64;
    const int tx = (tid & 15) << 2, ty = (tid >> 4) << 2;
    const int lr = tid >> 2, lk = (tid & 3) << 2;
    const int bkr = tid >> 4, bnc = (tid & 15) << 2;
    float acc[4][4] = {};

    for (int k0 = 0; k0 < K; k0 += 16) {
        float4 av = *(const float4*)(A + (size_t)(m0 + lr) * K + k0 + lk);
        As[lk+0][lr] = av.x; As[lk+1][lr] = av.y; As[lk+2][lr] = av.z; As[lk+3][lr] = av.w;
        float4 bv = *(const float4*)(Bm + (size_t)(k0 + bkr) * N + n0 + bnc);
        *(float4*)(&Bs[bkr][bnc]) = bv;
        __syncthreads();
#pragma unroll
        for (int kk = 0; kk < 16; kk++) {
            float4 a = *(const float4*)(&As[kk][ty]);
            float4 b = *(const float4*)(&Bs[kk][tx]);
            acc[0][0] += a.x*b.x; acc[0][1] += a.x*b.y; acc[0][2] += a.x*b.z; acc[0][3] += a.x*b.w;
            acc[1][0] += a.y*b.x; acc[1][1] += a.y*b.y; acc[1][2] += a.y*b.z; acc[1][3] += a.y*b.w;
            acc[2][0] += a.z*b.x; acc[2][1] += a.z*b.y; acc[2][2] += a.z*b.z; acc[2][3] += a.z*b.w;
            acc[3][0] += a.w*b.x; acc[3][1] += a.w*b.y; acc[3][2] += a.w*b.z; acc[3][3] += a.w*b.w;
        }
        __syncthreads();
    }
#pragma unroll
    for (int i = 0; i < 4; i++) {
        float4 o = {acc[i][0], acc[i][1], acc[i][2], acc[i][3]};
        *(float4*)(C + (size_t)(m0+ty+i) * N + n0 + tx) = o;
    }
}

// ---------------- prep: xcat + maxpool + h0 + counter reset ----------------
__global__ void prep_kernel(const float* __restrict__ attn_mem,
                            const float* __restrict__ lstm_in,
                            const float* __restrict__ init_h,
                            const int* __restrict__ msz)
{
    const int t = blockIdx.x, b = blockIdx.y, d = threadIdx.x;
    if (t == 0) {
        if (b == 0 && d <= TT) g_cnt[d] = 0u;   // stream-ordered before lstm_kernel
        const int ms = msz[b];
        float m = -3.0e38f;
        for (int n = 0; n < ms; n++)
            m = fmaxf(m, attn_mem[((size_t)b * NSS + n) * DD + d]);
        g_xcat[(size_t)b * DD + d] = m;
        g_hbuf[0][b * HH + d] = init_h[d];
    } else {
        g_xcat[((size_t)t * BB + b) * DD + d] =
            lstm_in[((size_t)b * (TT - 1) + (t - 1)) * DD + d];
    }
}

// ---------------- persistent LSTM: 128 CTAs, release/acquire counter barrier ----------------
__global__ void __launch_bounds__(256) lstm_kernel(const float* __restrict__ Whh,
                                                   const float* __restrict__ init_c)
{
    __shared__ float h_sm[16][516];        // 33 KB; aliased as red after compute
    __shared__ float gsm[16][16];
    __shared__ float c_sm[16][4];

    float* red = &h_sm[0][0];              // [16 kc][260] scratch (aliased)

    const int tid = threadIdx.x;
    const int hd0 = blockIdx.x * 4;
    const int kc = tid & 15;
    const int rr = (tid >> 4) & 3;
    const int bq = tid >> 6;

    const float* wp0 = Whh + ((size_t)(0*HH + hd0 + rr)) * HH + kc * 4;
    const float* wp1 = Whh + ((size_t)(1*HH + hd0 + rr)) * HH + kc * 4;
    const float* wp2 = Whh + ((size_t)(2*HH + hd0 + rr)) * HH + kc * 4;
    const float* wp3 = Whh + ((size_t)(3*HH + hd0 + rr)) * HH + kc * 4;

    if (tid < 64) { int b = tid >> 2, l = tid & 3; c_sm[b][l] = init_c[hd0 + l]; }

    const int rowX = tid >> 4;
    const int bX   = tid & 15;

    for (int s = 0; s < TT; s++) {
        // prefetch this step's X preactivation (independent of h)
        float xv = __ldcg(&g_X[((size_t)s * BB + bX) * (4 * HH) + (rowX >> 2) * HH + hd0 + (rowX & 3)]);

        if (s > 0) {
            if (tid == 0) {
                while (ld_acquire(&g_cnt[s - 1]) < (unsigned)NB_LSTM) { }
            }
        }
        __syncthreads();   // broadcasts tid0's acquire ordering CTA-wide

        // stage h into h_sm[b][k]
        const float4* hb = (const float4*)g_hbuf[s & 1];
#pragma unroll
        for (int i2 = 0; i2 < 8; i2++) {
            int i = tid + 256 * i2;
            float4 hv = __ldcg(hb + i);
            int b = i >> 7, k4 = (i & 127) << 2;
            *(float4*)(&h_sm[b][k4]) = hv;
        }
        __syncthreads();

        unsigned long long acc[4][4];
#pragma unroll
        for (int g = 0; g < 4; g++)
#pragma unroll
            for (int bi = 0; bi < 4; bi++) acc[g][bi] = 0ULL;

#pragma unroll
        for (int j = 0; j < 8; j++) {
            const ulonglong2 w0 = *(const ulonglong2*)(wp0 + j * 64);
            const ulonglong2 w1 = *(const ulonglong2*)(wp1 + j * 64);
            const ulonglong2 w2 = *(const ulonglong2*)(wp2 + j * 64);
            const ulonglong2 w3 = *(const ulonglong2*)(wp3 + j * 64);
#pragma unroll
            for (int bi = 0; bi < 4; bi++) {
                const ulonglong2 h2 = *(const ulonglong2*)(&h_sm[bq * 4 + bi][kc * 4 + j * 64]);
                acc[0][bi] = ffma2(w0.x, h2.x, acc[0][bi]);
                acc[0][bi] = ffma2(w0.y, h2.y, acc[0][bi]);
                acc[1][bi] = ffma2(w1.x, h2.x, acc[1][bi]);
                acc[1][bi] = ffma2(w1.y, h2.y, acc[1][bi]);
                acc[2][bi] = ffma2(w2.x, h2.x, acc[2][bi]);
                acc[2][bi] = ffma2(w2.y, h2.y, acc[2][bi]);
                acc[3][bi] = ffma2(w3.x, h2.x, acc[3][bi]);
                acc[3][bi] = ffma2(w3.y, h2.y, acc[3][bi]);
            }
        }
        __syncthreads();   // h_sm reads done before aliasing as red

#pragma unroll
        for (int g = 0; g < 4; g++)
#pragma unroll
            for (int bi = 0; bi < 4; bi++)
                red[kc * 260 + (g * 4 + rr) * 16 + (bq * 4 + bi)] = pairsum(acc[g][bi]);
        __syncthreads();

        {
            float sum = xv;
#pragma unroll
            for (int i = 0; i < 16; i++) sum += red[i * 260 + rowX * 16 + bX];
            gsm[rowX][bX] = sum;
        }
        __syncthreads();

        if (tid < 64) {
            int b = tid >> 2, l = tid & 3;
            float gi = gsm[0 + l][b], gf = gsm[4 + l][b];
            float gg = gsm[8 + l][b], go = gsm[12 + l][b];
            float c = sigm(gf) * c_sm[b][l] + sigm(gi) * fast_tanh(gg);
            float h = sigm(go) * fast_tanh(c);
            c_sm[b][l] = c;
            g_hbuf[(s + 1) & 1][b * HH + hd0 + l] = h;
            g_qa[((size_t)b * TT + s) * HH + hd0 + l] = h;
        }
        __syncthreads();   // h stores complete CTA-wide before the release below
        if (tid == 0 && s < TT - 1) {
            atom_add_release(&g_cnt[s]);   // publish: release orders prior h writes
        }
    }
}

// ---------------- hop: 8 t per block; score+softmax+weighted-sum fused ----------------
__global__ void __launch_bounds__(256) hop_kernel(
    const float* __restrict__ qw, const float* __restrict__ feat,
    const float* __restrict__ v, const int* __restrict__ msz,
    float* __restrict__ qout)
{
    __shared__ float qsm[8 * HH];
    __shared__ float vsm[HH];
    __shared__ float p[8][NSS];
    __shared__ float4 part[8][HH / 4];

    const int tg = blockIdx.x, b = blockIdx.y, tid = threadIdx.x;
    const int t0 = tg * 8;
    const float* qbase = qw + ((size_t)b * TT + t0) * HH;
    {
        const float4* qsrc = reinterpret_cast<const float4*>(qbase);
        float4* qdst = reinterpret_cast<float4*>(qsm);
#pragma unroll
        for (int i = 0; i < 4; i++) qdst[tid + 256 * i] = qsrc[tid + 256 * i];
        vsm[tid] = v[tid]; vsm[tid + 256] = v[tid + 256];
    }
    __syncthreads();

    const int wid = tid >> 5, lane = tid & 31;
    const int ms = msz[b];
    const float* qt = qsm + wid * HH;
    for (int n = 0; n < NSS; n++) {
        const float* f = feat + ((size_t)b * NSS + n) * HH;
        float s = 0.f;
#pragma unroll 4
        for (int j = 0; j < 16; j++) {
            int k = lane + (j << 5);
            s += vsm[k] * fast_tanh(f[k] + qt[k]);
        }
#pragma unroll
        for (int o = 16; o; o >>= 1) s += __shfl_xor_sync(0xffffffffu, s, o);
        if (lane == 0) p[wid][n] = (n < ms) ? s : -1e30f;
    }
    __syncthreads();
    {
        float x0 = p[wid][lane], x1 = p[wid][lane+32], x2 = p[wid][lane+64], x3 = p[wid][lane+96];
        float m = fmaxf(fmaxf(x0, x1), fmaxf(x2, x3));
#pragma unroll
        for (int o = 16; o; o >>= 1) m = fmaxf(m, __shfl_xor_sync(0xffffffffu, m, o));
        float e0 = __expf(x0 - m), e1 = __expf(x1 - m), e2 = __expf(x2 - m), e3 = __expf(x3 - m);
        float s = e0 + e1 + e2 + e3;
#pragma unroll
        for (int o = 16; o; o >>= 1) s += __shfl_xor_sync(0xffffffffu, s, o);
        float inv = 1.f / s;
        p[wid][lane] = e0*inv; p[wid][lane+32] = e1*inv; p[wid][lane+64] = e2*inv; p[wid][lane+96] = e3*inv;
    }
    __syncthreads();
    {
        const int g = tid >> 7;
        const int hc = tid & 127;
        float4 acc[8] = {};
        const int nlo = g * 64;
#pragma unroll 2
        for (int n = nlo; n < nlo + 64; n++) {
            float4 fv = *reinterpret_cast<const float4*>(feat + ((size_t)b * NSS + n) * HH + hc * 4);
#pragma unroll
            for (int t = 0; t < 8; t++) {
                float pw = p[t][n];
                acc[t].x = fmaf(pw, fv.x, acc[t].x);
                acc[t].y = fmaf(pw, fv.y, acc[t].y);
                acc[t].z = fmaf(pw, fv.z, acc[t].z);
                acc[t].w = fmaf(pw, fv.w, acc[t].w);
            }
        }
        if (g == 1) {
#pragma unroll
            for (int t = 0; t < 8; t++) part[t][hc] = acc[t];
        }
        __syncthreads();
        if (g == 0) {
#pragma unroll
            for (int t = 0; t < 8; t++) {
                float4 pv = part[t][hc];
                float4 o = {acc[t].x + pv.x, acc[t].y + pv.y, acc[t].z + pv.z, acc[t].w + pv.w};
                *reinterpret_cast<float4*>(qout + ((size_t)b * TT + t0 + t) * HH + hc * 4) = o;
            }
        }
    }
}

// ---------------- final score (unmasked) ----------------
__global__ void __launch_bounds__(256) final_kernel(
    const float* __restrict__ qw, const float* __restrict__ feat,
    const float* __restrict__ v, float* __restrict__ out)
{
    __shared__ float qsm[HH];
    __shared__ float vsm[HH];
    const int t = blockIdx.x, b = blockIdx.y, tid = threadIdx.x;
    const float* qrow = qw + ((size_t)b * TT + t) * HH;
    qsm[tid] = qrow[tid]; qsm[tid + 256] = qrow[tid + 256];
    vsm[tid] = v[tid];    vsm[tid + 256] = v[tid + 256];
    __syncthreads();
    const int wid = tid >> 5, lane = tid & 31;
    for (int n = wid; n < NSS; n += 8) {
        const float* f = feat + ((size_t)b * NSS + n) * HH;
        float s = 0.f;
#pragma unroll 4
        for (int j = 0; j < 16; j++) {
            int k = lane + (j << 5);
            s += vsm[k] * fast_tanh(f[k] + qsm[k]);
        }
#pragma unroll
        for (int o = 16; o; o >>= 1) s += __shfl_xor_sync(0xffffffffu, s, o);
        if (lane == 0) out[(((size_t)b * TT) + t) * NSS + n] = s;
    }
}

extern "C" void kernel_launch(void* const* d_in, const int* in_sizes, int n_in,
                              void* d_out, int out_size)
{
    const float* attn_mem = (const float*)d_in[0];
    const float* lstm_in  = (const float*)d_in[1];
    const float* init_h   = (const float*)d_in[2];
    const float* init_c   = (const float*)d_in[3];
    const float* Wih      = (const float*)d_in[4];
    const float* Whh      = (const float*)d_in[5];
    const float* bih      = (const float*)d_in[6];
    const float* bhh      = (const float*)d_in[7];
    const float* attn_wm  = (const float*)d_in[8];
    const float* attn_wq  = (const float*)d_in[9];
    const float* attn_v   = (const float*)d_in[10];
    const float* hop_wm   = (const float*)d_in[11];
    const float* hop_wq   = (const float*)d_in[12];
    const float* hop_v    = (const float*)d_in[13];
    const int*   msz      = (const int*)d_in[14];
    float* out = (float*)d_out;

    float *afeat, *hfeat, *xcat, *X, *qa, *qb, *qwb;
    cudaGetSymbolAddress((void**)&afeat, g_attn_feat);
    cudaGetSymbolAddress((void**)&hfeat, g_hop_feat);
    cudaGetSymbolAddress((void**)&xcat,  g_xcat);
    cudaGetSymbolAddress((void**)&X,     g_X);
    cudaGetSymbolAddress((void**)&qa,    g_qa);
    cudaGetSymbolAddress((void**)&qb,    g_qb);
    cudaGetSymbolAddress((void**)&qwb,   g_qw);

    prep_kernel<<<dim3(TT, BB), DD>>>(attn_mem, lstm_in, init_h, msz);
    sgemm_big<false,false><<<dim3(4, 16, 2), 256>>>(attn_mem, attn_wm, hop_wm,
                                                    nullptr, nullptr, afeat, hfeat,
                                                    BB*NSS, HH, DD);
    sgemm_big<true, true ><<<dim3(16, 8, 1), 256>>>(xcat, Wih, nullptr,
                                                    bih, bhh, X, nullptr,
                                                    TT*BB, 4*HH, DD);
    lstm_kernel<<<NB_LSTM, 256>>>(Whh, init_c);
    // hop 1
    sgemm_small<<<dim3(8, 16), 256>>>(qa, hop_wq, qwb, BB*TT, HH, HH);
    hop_kernel<<<dim3(8, BB), 256>>>(qwb, hfeat, hop_v, msz, qb);
    // hop 2
    sgemm_small<<<dim3(8, 16), 256>>>(qb, hop_wq, qwb, BB*TT, HH, HH);
    hop_kernel<<<dim3(8, BB), 256>>>(qwb, hfeat, hop_v, msz, qa);
    // final
    sgemm_small<<<dim3(8, 16), 256>>>(qa, attn_wq, qwb, BB*TT, HH, HH);
    final_kernel<<<dim3(TT, BB), 256>>>(qwb, afeat, attn_v, out);
}